// round 12
// baseline (speedup 1.0000x reference)
#include <cuda_runtime.h>
#include <math.h>

// Row-normalize: out[r, :] = in[r, :] * inv(sum(in[r, :])), inv->0 if non-finite.
// Row length fixed at 1024 f32 = 256 float4. One warp per row:
// each lane owns 8 float4 (32 floats), single pass (load -> reduce -> scale -> store).

#define ROW_LEN 1024
#define VEC_PER_ROW (ROW_LEN / 4)      // 256 float4
#define VEC_PER_LANE (VEC_PER_ROW / 32) // 8 float4 per lane
#define WARPS_PER_BLOCK 8
#define THREADS_PER_BLOCK (WARPS_PER_BLOCK * 32)

__global__ __launch_bounds__(THREADS_PER_BLOCK)
void normalizer_kernel(const float4* __restrict__ in,
                       float4* __restrict__ out,
                       int n_rows)
{
    const int warp_id = threadIdx.x >> 5;
    const int lane    = threadIdx.x & 31;
    const int row     = blockIdx.x * WARPS_PER_BLOCK + warp_id;
    if (row >= n_rows) return;

    const float4* row_in  = in  + (size_t)row * VEC_PER_ROW;
    float4*       row_out = out + (size_t)row * VEC_PER_ROW;

    // Front-batched loads: 8 independent LDG.128 per lane (MLP=8).
    float4 v[VEC_PER_LANE];
#pragma unroll
    for (int k = 0; k < VEC_PER_LANE; k++) {
        v[k] = row_in[lane + k * 32];
    }

    // Per-lane partial sum.
    float s = 0.0f;
#pragma unroll
    for (int k = 0; k < VEC_PER_LANE; k++) {
        s += (v[k].x + v[k].y) + (v[k].z + v[k].w);
    }

    // Warp reduction (butterfly -> all lanes hold the full row sum).
#pragma unroll
    for (int off = 16; off > 0; off >>= 1) {
        s += __shfl_xor_sync(0xFFFFFFFFu, s, off);
    }

    float inv = 1.0f / s;
    if (!isfinite(inv)) inv = 0.0f;

    // Scale from registers and store.
#pragma unroll
    for (int k = 0; k < VEC_PER_LANE; k++) {
        float4 o;
        o.x = v[k].x * inv;
        o.y = v[k].y * inv;
        o.z = v[k].z * inv;
        o.w = v[k].w * inv;
        row_out[lane + k * 32] = o;
    }
}

extern "C" void kernel_launch(void* const* d_in, const int* in_sizes, int n_in,
                              void* d_out, int out_size)
{
    const float4* in  = (const float4*)d_in[0];
    float4*       out = (float4*)d_out;

    const int total  = in_sizes[0];          // 2*32*1024*1024 = 67108864
    const int n_rows = total / ROW_LEN;      // 65536

    const int blocks = (n_rows + WARPS_PER_BLOCK - 1) / WARPS_PER_BLOCK; // 8192
    normalizer_kernel<<<blocks, THREADS_PER_BLOCK>>>(in, out, n_rows);
}

// round 13
// speedup vs baseline: 1.0008x; 1.0008x over previous
#include <cuda_runtime.h>
#include <math.h>

// Row-normalize: out[r, :] = in[r, :] * inv(sum(in[r, :])), inv->0 if non-finite.
// Row length fixed at 1024 f32 = 256 float4. One warp per row:
// each lane owns 8 float4 (32 floats), single pass (load -> reduce -> scale -> store).
// R12: streaming cache hints (.cs) on the global loads/stores — data is touched
// exactly once, so evict-first minimizes L2 churn on a pure 512MB stream.

#define ROW_LEN 1024
#define VEC_PER_ROW (ROW_LEN / 4)       // 256 float4
#define VEC_PER_LANE (VEC_PER_ROW / 32) // 8 float4 per lane
#define WARPS_PER_BLOCK 8
#define THREADS_PER_BLOCK (WARPS_PER_BLOCK * 32)

__global__ __launch_bounds__(THREADS_PER_BLOCK)
void normalizer_kernel(const float4* __restrict__ in,
                       float4* __restrict__ out,
                       int n_rows)
{
    const int warp_id = threadIdx.x >> 5;
    const int lane    = threadIdx.x & 31;
    const int row     = blockIdx.x * WARPS_PER_BLOCK + warp_id;
    if (row >= n_rows) return;

    const float4* row_in  = in  + (size_t)row * VEC_PER_ROW;
    float4*       row_out = out + (size_t)row * VEC_PER_ROW;

    // Front-batched streaming loads: 8 independent LDG.128.CS per lane (MLP=8).
    float4 v[VEC_PER_LANE];
#pragma unroll
    for (int k = 0; k < VEC_PER_LANE; k++) {
        v[k] = __ldcs(&row_in[lane + k * 32]);
    }

    // Per-lane partial sum.
    float s = 0.0f;
#pragma unroll
    for (int k = 0; k < VEC_PER_LANE; k++) {
        s += (v[k].x + v[k].y) + (v[k].z + v[k].w);
    }

    // Warp reduction (butterfly -> all lanes hold the full row sum).
#pragma unroll
    for (int off = 16; off > 0; off >>= 1) {
        s += __shfl_xor_sync(0xFFFFFFFFu, s, off);
    }

    float inv = 1.0f / s;
    if (!isfinite(inv)) inv = 0.0f;

    // Scale from registers and store with evict-first policy.
#pragma unroll
    for (int k = 0; k < VEC_PER_LANE; k++) {
        float4 o;
        o.x = v[k].x * inv;
        o.y = v[k].y * inv;
        o.z = v[k].z * inv;
        o.w = v[k].w * inv;
        __stcs(&row_out[lane + k * 32], o);
    }
}

extern "C" void kernel_launch(void* const* d_in, const int* in_sizes, int n_in,
                              void* d_out, int out_size)
{
    const float4* in  = (const float4*)d_in[0];
    float4*       out = (float4*)d_out;

    const int total  = in_sizes[0];          // 2*32*1024*1024 = 67108864
    const int n_rows = total / ROW_LEN;      // 65536

    const int blocks = (n_rows + WARPS_PER_BLOCK - 1) / WARPS_PER_BLOCK; // 8192
    normalizer_kernel<<<blocks, THREADS_PER_BLOCK>>>(in, out, n_rows);
}